// round 4
// baseline (speedup 1.0000x reference)
#include <cuda_runtime.h>

// Problem shape (fixed by the dataset reference)
#define BB      16
#define TT      256
#define NPTS    2048
#define NF      (NPTS * 3)             // 6144 flat (point,coord) indices
#define TCHUNK  32
#define NCHUNKS (TT / TCHUNK)          // 8
#define BC      (BB * NCHUNKS)         // 128 partial groups
#define THREADS 128
#define FPT     4                      // flats per thread (float4)
#define CPB     (NF / (THREADS * FPT)) // 12 CTAs per bc group
#define NCTA    (BC * CPB)             // 1536 main CTAs
#define RFIN    128                    // finish CTAs
#define PTSPC   (NPTS / RFIN)          // 16 points per finish CTA
#define FLATSPC (PTSPC * 3)            // 48 flats per finish CTA

// Partial per-(n,c) stats: g_part[bc][stat][flat], stat: 0 sxp, 1 ssp, 2 sxg, 3 ssg, 4 cnt
__device__ float  g_part[BC * 5 * NF];      // 15.7 MB, fully overwritten each replay
__device__ float4 g_pscal[NCTA];            // per-CTA: cnt3x, recon, vels, velc3x
__device__ float  g_fin[RFIN * 5];          // per-finish-CTA: id, cnt3x, recon, vels, velc3x
__device__ unsigned g_ctr;                  // last-block counter (self-resetting)

__global__ __launch_bounds__(THREADS) void main_k(
    const float* __restrict__ pred,
    const float* __restrict__ gt,
    const float* __restrict__ vis)
{
    const int bc    = blockIdx.x / CPB;
    const int sub   = blockIdx.x - bc * CPB;
    const int flat4 = sub * (THREADS * FPT) + threadIdx.x * FPT;
    const int chunk = bc & (NCHUNKS - 1);
    const int b     = bc >> 3;                 // NCHUNKS = 8
    const int t0    = chunk * TCHUNK;

    // component invariants: component j -> point nA+sel_j, coord c_j, weight w_j
    const int nA = flat4 / 3;
    const int c0 = flat4 - 3 * nA;
    float sel[FPT], w[FPT];
#pragma unroll
    for (int j = 0; j < FPT; ++j) {
        int cj = c0 + j;
        int s  = (cj >= 3) ? 1 : 0;
        sel[j] = (float)s;
        int cc = cj - 3 * s;
        w[j]   = (cc == 2) ? 2.f : 1.f;
    }

    const int row0 = b * TT + t0;
    const float4* pp = (const float4*)(pred + (long)row0 * NF) + (flat4 >> 2);
    const float4* gp = (const float4*)(gt   + (long)row0 * NF) + (flat4 >> 2);
    const float*  vp = vis + (long)row0 * NPTS + nA;

    float sxp[FPT] = {0,0,0,0}, ssp[FPT] = {0,0,0,0};
    float sxg[FPT] = {0,0,0,0}, ssg[FPT] = {0,0,0,0};
    float cnt[FPT] = {0,0,0,0};
    float pd[FPT]  = {0,0,0,0}, pm[FPT] = {0,0,0,0};
    float recon = 0.f, vels = 0.f, velc = 0.f;

    if (t0 > 0) {
        float4 p = pp[-(NF / 4)];
        float4 g = gp[-(NF / 4)];
        float mA = (vp[-NPTS] > 0.5f) ? 1.f : 0.f;
        float mB = (vp[-NPTS + 1] > 0.5f) ? 1.f : 0.f;
        float pa[FPT] = {p.x, p.y, p.z, p.w};
        float ga[FPT] = {g.x, g.y, g.z, g.w};
#pragma unroll
        for (int j = 0; j < FPT; ++j) {
            pm[j] = mA + sel[j] * (mB - mA);
            pd[j] = pa[j] - ga[j];
        }
    }

#pragma unroll 2
    for (int t = 0; t < TCHUNK; ++t) {
        float4 p = pp[0];
        float4 g = gp[0];
        float vA = vp[0], vB = vp[1];
        pp += NF / 4; gp += NF / 4; vp += NPTS;

        float mA = (vA > 0.5f) ? 1.f : 0.f;
        float mB = (vB > 0.5f) ? 1.f : 0.f;
        float pa[FPT] = {p.x, p.y, p.z, p.w};
        float ga[FPT] = {g.x, g.y, g.z, g.w};

#pragma unroll
        for (int j = 0; j < FPT; ++j) {
            float m = mA + sel[j] * (mB - mA);
            float pv = pa[j], gv = ga[j];
            float d = pv - gv;

            recon  += w[j] * (m * d) * d;
            cnt[j] += m;

            float mp = m * pv, mg = m * gv;
            sxp[j] += mp;  ssp[j] += mp * pv;
            sxg[j] += mg;  ssg[j] += mg * gv;

            float vm = m * pm[j];
            float tv = d - pd[j];
            vels += (vm * tv) * tv;
            velc += vm;

            pd[j] = d; pm[j] = m;
        }
    }

    // per-(n,c) stats -> partial buffer (vectorized coalesced stores, no atomics)
    {
        float* gbase = &g_part[(long)bc * 5 * NF + flat4];
        *(float4*)(gbase + 0 * NF) = make_float4(sxp[0], sxp[1], sxp[2], sxp[3]);
        *(float4*)(gbase + 1 * NF) = make_float4(ssp[0], ssp[1], ssp[2], ssp[3]);
        *(float4*)(gbase + 2 * NF) = make_float4(sxg[0], sxg[1], sxg[2], sxg[3]);
        *(float4*)(gbase + 3 * NF) = make_float4(ssg[0], ssg[1], ssg[2], ssg[3]);
        *(float4*)(gbase + 4 * NF) = make_float4(cnt[0], cnt[1], cnt[2], cnt[3]);
    }

    // scalar partials: warp reduce -> smem -> one float4 store per CTA
    float cs = cnt[0] + cnt[1] + cnt[2] + cnt[3];
    const unsigned fmask = 0xffffffffu;
    __shared__ float swarp[4][4];
#pragma unroll
    for (int o = 16; o > 0; o >>= 1) {
        cs    += __shfl_down_sync(fmask, cs,    o);
        recon += __shfl_down_sync(fmask, recon, o);
        vels  += __shfl_down_sync(fmask, vels,  o);
        velc  += __shfl_down_sync(fmask, velc,  o);
    }
    int wd = threadIdx.x >> 5;
    if ((threadIdx.x & 31) == 0) {
        swarp[wd][0] = cs; swarp[wd][1] = recon; swarp[wd][2] = vels; swarp[wd][3] = velc;
    }
    __syncthreads();
    if (threadIdx.x == 0) {
        float s0 = 0.f, s1 = 0.f, s2 = 0.f, s3 = 0.f;
#pragma unroll
        for (int i = 0; i < 4; ++i) {
            s0 += swarp[i][0]; s1 += swarp[i][1]; s2 += swarp[i][2]; s3 += swarp[i][3];
        }
        g_pscal[blockIdx.x] = make_float4(s0, s1, s2, s3);
    }
}

// Fused finish: reduce partials over bc, compute identity, fold scalars,
// last block combines everything and writes the 4 outputs.
__global__ __launch_bounds__(256) void finish_k(float* __restrict__ out)
{
    const int t  = threadIdx.x;
    const int bx = blockIdx.x;
    const int f0 = bx * FLATSPC;

    __shared__ float sstat[5][FLATSPC];
    __shared__ float part5[5];
    __shared__ bool  islast;

    // Stage A: reduce over bc for this CTA's 5 x 48 (stat, flat) pairs
    if (t < 5 * FLATSPC) {
        int stat = t / FLATSPC;
        int fo   = t - stat * FLATSPC;
        const float* base = g_part + (long)stat * NF + (f0 + fo);
        float s = 0.f;
#pragma unroll 4
        for (int bc = 0; bc < BC; ++bc)
            s += base[(long)bc * 5 * NF];
        sstat[stat][fo] = s;
    }
    __syncthreads();

    // Stage B (warp 0): identity contributions for this CTA's 16 points
    float idp = 0.f;
    if (t < PTSPC) {
        int fo = t * 3;
        float cn = sstat[4][fo];
        if (cn > 1.f) {
            float inv_n  = 1.f / cn;
            float inv_n1 = 1.f / (cn - 1.f);
            float adsum = 0.f, vgsum = 0.f;
#pragma unroll
            for (int k = 0; k < 3; ++k) {
                float sp  = sstat[0][fo + k];
                float ssp = sstat[1][fo + k];
                float sg  = sstat[2][fo + k];
                float ssg = sstat[3][fo + k];
                float vp = (ssp - sp * sp * inv_n) * inv_n1;
                float vg = (ssg - sg * sg * inv_n) * inv_n1;
                adsum += fabsf(vp - vg);
                vgsum += vg;
            }
            idp = adsum / (vgsum + 1e-6f);
        }
    }
    if (t < 32) {
#pragma unroll
        for (int o = 16; o > 0; o >>= 1)
            idp += __shfl_down_sync(0xffffffffu, idp, o);
        if (t == 0) part5[0] = idp;
    }

    // Stage C (warp 2): fold this CTA's slice of main-kernel scalar partials
    if (t >= 64 && t < 96) {
        int lane = t - 64;                          // 0..31, entries 0..11 valid
        float4 v = make_float4(0.f, 0.f, 0.f, 0.f);
        if (lane < NCTA / RFIN)                     // 12 entries per finish CTA
            v = g_pscal[bx * (NCTA / RFIN) + lane];
#pragma unroll
        for (int o = 16; o > 0; o >>= 1) {
            v.x += __shfl_down_sync(0xffffffffu, v.x, o);
            v.y += __shfl_down_sync(0xffffffffu, v.y, o);
            v.z += __shfl_down_sync(0xffffffffu, v.z, o);
            v.w += __shfl_down_sync(0xffffffffu, v.w, o);
        }
        if (lane == 0) {
            part5[1] = v.x; part5[2] = v.y; part5[3] = v.z; part5[4] = v.w;
        }
    }
    __syncthreads();

    if (t < 5) g_fin[bx * 5 + t] = part5[t];
    __threadfence();
    if (t == 0) {
        unsigned old = atomicAdd(&g_ctr, 1u);
        islast = (old == RFIN - 1);
    }
    __syncthreads();

    if (islast) {
        __threadfence();
        __shared__ float red[5][RFIN];
        float a0 = 0.f, a1 = 0.f, a2 = 0.f, a3 = 0.f, a4 = 0.f;
        if (t < RFIN) {
            const float* f = &g_fin[t * 5];
            a0 = __ldcg(f + 0); a1 = __ldcg(f + 1); a2 = __ldcg(f + 2);
            a3 = __ldcg(f + 3); a4 = __ldcg(f + 4);
        }
        red[0][t & (RFIN - 1)] = a0; red[1][t & (RFIN - 1)] = a1;
        red[2][t & (RFIN - 1)] = a2; red[3][t & (RFIN - 1)] = a3;
        red[4][t & (RFIN - 1)] = a4;
        // threads 128..255 wrote duplicates of 0..127? avoid: only t<128 wrote real data
        if (t >= RFIN) { red[0][t - RFIN] = red[0][t - RFIN]; } // no-op
        __syncthreads();
#pragma unroll
        for (int s = RFIN / 2; s > 0; s >>= 1) {
            if (t < s) {
#pragma unroll
                for (int k = 0; k < 5; ++k)
                    red[k][t] += red[k][t + s];
            }
            __syncthreads();
        }

        if (t == 0) {
            float identity = red[0][0] / (float)NPTS;
            float nv = red[1][0] / 3.0f;   // counts accumulated once per coord
            float rs = red[2][0];
            float vs = red[3][0];
            float vc = red[4][0] / 3.0f;
            float recon    = (nv > 0.f) ? rs / fmaxf(nv, 1.f) : 0.f;
            float temporal = (vc > 0.f) ? vs / fmaxf(vc, 1.f) : 0.f;

            // adaptive re-weighting (faithful to reference)
            float rl = recon, tl = temporal, il = identity;
            bool  all_pos = (rl > 0.f) && (tl > 0.f) && (il > 0.f);
            float maxc    = fmaxf(rl, fmaxf(tl, il));
            float target  = maxc / 3.f;
            float thresh  = 10.f * target;
            float rw = (all_pos && rl > thresh) ? 1.0f * target / fmaxf(rl, 1e-30f) : 1.0f;
            float tw = (all_pos && tl > thresh) ? 0.5f * target / fmaxf(tl, 1e-30f) : 0.5f;
            float iw = (all_pos && il > thresh) ? 0.1f * target / fmaxf(il, 1e-30f) : 0.1f;

            out[0] = rw * recon + tw * temporal + iw * identity;
            out[1] = recon;
            out[2] = temporal;
            out[3] = identity;

            g_ctr = 0;   // self-reset for next graph replay
        }
    }
}

extern "C" void kernel_launch(void* const* d_in, const int* in_sizes, int n_in,
                              void* d_out, int out_size)
{
    const float* pred = (const float*)d_in[0];
    const float* gt   = (const float*)d_in[1];
    const float* vis  = (const float*)d_in[2];
    float* out = (float*)d_out;
    (void)in_sizes; (void)n_in; (void)out_size;

    main_k<<<NCTA, THREADS>>>(pred, gt, vis);      // 1536 blocks
    finish_k<<<RFIN, 256>>>(out);                  // 128 blocks, fused tail
}

// round 5
// speedup vs baseline: 1.1257x; 1.1257x over previous
#include <cuda_runtime.h>

// Problem shape (fixed by the dataset reference)
#define BB      16
#define TT      256
#define NPTS    2048
#define NF      (NPTS * 3)             // 6144 flat (point,coord) indices
#define TCHUNK  32
#define NCHUNKS (TT / TCHUNK)          // 8
#define BC      (BB * NCHUNKS)         // 128 partial groups
#define THREADS 128
#define FPT     4                      // flats per thread (float4)
#define CPB     (NF / (THREADS * FPT)) // 12 CTAs per bc group
#define NCTA    (BC * CPB)             // 1536 main CTAs
#define RFIN    128                    // finish CTAs
#define PTSPC   (NPTS / RFIN)          // 16 points per finish CTA
#define FLATSPC (PTSPC * 3)            // 48 flats per finish CTA

// Partial per-(n,c) stats: g_part[bc][stat][flat], stat: 0 sxp, 1 ssp, 2 sxg, 3 ssg, 4 cnt
__device__ float  g_part[BC * 5 * NF];      // 15.7 MB, fully overwritten each replay
__device__ float4 g_pscal[NCTA];            // per-CTA: cnt3x, recon, vels, velc3x
__device__ float  g_fin[RFIN * 5];          // per-finish-CTA: id, cnt3x, recon, vels, velc3x
__device__ unsigned g_ctr;                  // last-block counter (self-resetting)

__global__ __launch_bounds__(THREADS) void main_k(
    const float* __restrict__ pred,
    const float* __restrict__ gt,
    const float* __restrict__ vis)
{
    const int bc    = blockIdx.x / CPB;
    const int sub   = blockIdx.x - bc * CPB;
    const int flat4 = sub * (THREADS * FPT) + threadIdx.x * FPT;
    const int chunk = bc & (NCHUNKS - 1);
    const int b     = bc >> 3;                 // NCHUNKS = 8
    const int t0    = chunk * TCHUNK;

    // component invariants: component j -> point nA+sel_j, coord c_j, weight w_j
    const int nA = flat4 / 3;
    const int c0 = flat4 - 3 * nA;
    float sel[FPT], w[FPT];
#pragma unroll
    for (int j = 0; j < FPT; ++j) {
        int cj = c0 + j;
        int s  = (cj >= 3) ? 1 : 0;
        sel[j] = (float)s;
        int cc = cj - 3 * s;
        w[j]   = (cc == 2) ? 2.f : 1.f;
    }

    const int row0 = b * TT + t0;
    const float4* pp = (const float4*)(pred + (long)row0 * NF) + (flat4 >> 2);
    const float4* gp = (const float4*)(gt   + (long)row0 * NF) + (flat4 >> 2);
    const float*  vp = vis + (long)row0 * NPTS + nA;

    float sxp[FPT] = {0,0,0,0}, ssp[FPT] = {0,0,0,0};
    float sxg[FPT] = {0,0,0,0}, ssg[FPT] = {0,0,0,0};
    float cnt[FPT] = {0,0,0,0};
    float pd[FPT]  = {0,0,0,0}, pm[FPT] = {0,0,0,0};
    float recon = 0.f, vels = 0.f, velc = 0.f;

    if (t0 > 0) {
        float4 p = pp[-(NF / 4)];
        float4 g = gp[-(NF / 4)];
        float mA = (vp[-NPTS] > 0.5f) ? 1.f : 0.f;
        float mB = (vp[-NPTS + 1] > 0.5f) ? 1.f : 0.f;
        float pa[FPT] = {p.x, p.y, p.z, p.w};
        float ga[FPT] = {g.x, g.y, g.z, g.w};
#pragma unroll
        for (int j = 0; j < FPT; ++j) {
            pm[j] = mA + sel[j] * (mB - mA);
            pd[j] = pa[j] - ga[j];
        }
    }

#pragma unroll 4
    for (int t = 0; t < TCHUNK; ++t) {
        float4 p = pp[0];
        float4 g = gp[0];
        float vA = vp[0], vB = vp[1];
        pp += NF / 4; gp += NF / 4; vp += NPTS;

        float mA = (vA > 0.5f) ? 1.f : 0.f;
        float mB = (vB > 0.5f) ? 1.f : 0.f;
        float pa[FPT] = {p.x, p.y, p.z, p.w};
        float ga[FPT] = {g.x, g.y, g.z, g.w};

#pragma unroll
        for (int j = 0; j < FPT; ++j) {
            float m = mA + sel[j] * (mB - mA);
            float pv = pa[j], gv = ga[j];
            float d = pv - gv;

            recon  += w[j] * (m * d) * d;
            cnt[j] += m;

            float mp = m * pv, mg = m * gv;
            sxp[j] += mp;  ssp[j] += mp * pv;
            sxg[j] += mg;  ssg[j] += mg * gv;

            float vm = m * pm[j];
            float tv = d - pd[j];
            vels += (vm * tv) * tv;
            velc += vm;

            pd[j] = d; pm[j] = m;
        }
    }

    // per-(n,c) stats -> partial buffer (vectorized coalesced stores, no atomics)
    {
        float* gbase = &g_part[(long)bc * 5 * NF + flat4];
        *(float4*)(gbase + 0 * NF) = make_float4(sxp[0], sxp[1], sxp[2], sxp[3]);
        *(float4*)(gbase + 1 * NF) = make_float4(ssp[0], ssp[1], ssp[2], ssp[3]);
        *(float4*)(gbase + 2 * NF) = make_float4(sxg[0], sxg[1], sxg[2], sxg[3]);
        *(float4*)(gbase + 3 * NF) = make_float4(ssg[0], ssg[1], ssg[2], ssg[3]);
        *(float4*)(gbase + 4 * NF) = make_float4(cnt[0], cnt[1], cnt[2], cnt[3]);
    }

    // scalar partials: warp reduce -> smem -> one float4 store per CTA
    float cs = cnt[0] + cnt[1] + cnt[2] + cnt[3];
    const unsigned fmask = 0xffffffffu;
    __shared__ float swarp[4][4];
#pragma unroll
    for (int o = 16; o > 0; o >>= 1) {
        cs    += __shfl_down_sync(fmask, cs,    o);
        recon += __shfl_down_sync(fmask, recon, o);
        vels  += __shfl_down_sync(fmask, vels,  o);
        velc  += __shfl_down_sync(fmask, velc,  o);
    }
    int wd = threadIdx.x >> 5;
    if ((threadIdx.x & 31) == 0) {
        swarp[wd][0] = cs; swarp[wd][1] = recon; swarp[wd][2] = vels; swarp[wd][3] = velc;
    }
    __syncthreads();
    if (threadIdx.x == 0) {
        float s0 = 0.f, s1 = 0.f, s2 = 0.f, s3 = 0.f;
#pragma unroll
        for (int i = 0; i < 4; ++i) {
            s0 += swarp[i][0]; s1 += swarp[i][1]; s2 += swarp[i][2]; s3 += swarp[i][3];
        }
        g_pscal[blockIdx.x] = make_float4(s0, s1, s2, s3);
    }
}

// Fused finish: reduce partials over bc (split across 2 thread groups, deep MLP),
// compute identity, fold scalars, last block combines and writes the 4 outputs.
__global__ __launch_bounds__(512) void finish_k(float* __restrict__ out)
{
    const int t  = threadIdx.x;
    const int bx = blockIdx.x;
    const int f0 = bx * FLATSPC;

    __shared__ float shalf[2][5][FLATSPC];
    __shared__ float part5[5];
    __shared__ bool  islast;

    // Stage A: threads 0..479 -> (half, stat, fo); each sums 64 bc values, unroll 16
    if (t < 2 * 5 * FLATSPC) {
        int half = t / (5 * FLATSPC);
        int rem  = t - half * (5 * FLATSPC);
        int stat = rem / FLATSPC;
        int fo   = rem - stat * FLATSPC;
        const float* base = g_part + (long)(half * (BC / 2)) * 5 * NF
                                   + (long)stat * NF + (f0 + fo);
        float s = 0.f;
#pragma unroll 16
        for (int bc = 0; bc < BC / 2; ++bc)
            s += base[(long)bc * 5 * NF];
        shalf[half][stat][fo] = s;
    }
    __syncthreads();

    // Stage B (warp 0): identity contributions for this CTA's 16 points
    float idp = 0.f;
    if (t < PTSPC) {
        int fo = t * 3;
        float cn = shalf[0][4][fo] + shalf[1][4][fo];
        if (cn > 1.f) {
            float inv_n  = 1.f / cn;
            float inv_n1 = 1.f / (cn - 1.f);
            float adsum = 0.f, vgsum = 0.f;
#pragma unroll
            for (int k = 0; k < 3; ++k) {
                float sp  = shalf[0][0][fo + k] + shalf[1][0][fo + k];
                float ssp = shalf[0][1][fo + k] + shalf[1][1][fo + k];
                float sg  = shalf[0][2][fo + k] + shalf[1][2][fo + k];
                float ssg = shalf[0][3][fo + k] + shalf[1][3][fo + k];
                float vp = (ssp - sp * sp * inv_n) * inv_n1;
                float vg = (ssg - sg * sg * inv_n) * inv_n1;
                adsum += fabsf(vp - vg);
                vgsum += vg;
            }
            idp = adsum / (vgsum + 1e-6f);
        }
    }
    if (t < 32) {
#pragma unroll
        for (int o = 16; o > 0; o >>= 1)
            idp += __shfl_down_sync(0xffffffffu, idp, o);
        if (t == 0) part5[0] = idp;
    }

    // Stage C (warp 15, idle in stages A-tail/B): fold main-kernel scalar partials
    if (t >= 480 && t < 512) {
        int lane = t - 480;                         // 0..31, entries 0..11 valid
        float4 v = make_float4(0.f, 0.f, 0.f, 0.f);
        if (lane < NCTA / RFIN)                     // 12 entries per finish CTA
            v = g_pscal[bx * (NCTA / RFIN) + lane];
#pragma unroll
        for (int o = 16; o > 0; o >>= 1) {
            v.x += __shfl_down_sync(0xffffffffu, v.x, o);
            v.y += __shfl_down_sync(0xffffffffu, v.y, o);
            v.z += __shfl_down_sync(0xffffffffu, v.z, o);
            v.w += __shfl_down_sync(0xffffffffu, v.w, o);
        }
        if (lane == 0) {
            part5[1] = v.x; part5[2] = v.y; part5[3] = v.z; part5[4] = v.w;
        }
    }
    __syncthreads();

    if (t < 5) g_fin[bx * 5 + t] = part5[t];
    __threadfence();
    if (t == 0) {
        unsigned old = atomicAdd(&g_ctr, 1u);
        islast = (old == RFIN - 1);
    }
    __syncthreads();

    if (islast) {
        __threadfence();
        __shared__ float red[5][RFIN];
        if (t < RFIN) {                    // ONLY t<128 touches red[] (race fixed)
            const float* f = &g_fin[t * 5];
            red[0][t] = __ldcg(f + 0);
            red[1][t] = __ldcg(f + 1);
            red[2][t] = __ldcg(f + 2);
            red[3][t] = __ldcg(f + 3);
            red[4][t] = __ldcg(f + 4);
        }
        __syncthreads();
#pragma unroll
        for (int s = RFIN / 2; s > 0; s >>= 1) {
            if (t < s) {
#pragma unroll
                for (int k = 0; k < 5; ++k)
                    red[k][t] += red[k][t + s];
            }
            __syncthreads();
        }

        if (t == 0) {
            float identity = red[0][0] / (float)NPTS;
            float nv = red[1][0] / 3.0f;   // counts accumulated once per coord
            float rs = red[2][0];
            float vs = red[3][0];
            float vc = red[4][0] / 3.0f;
            float recon    = (nv > 0.f) ? rs / fmaxf(nv, 1.f) : 0.f;
            float temporal = (vc > 0.f) ? vs / fmaxf(vc, 1.f) : 0.f;

            // adaptive re-weighting (faithful to reference)
            float rl = recon, tl = temporal, il = identity;
            bool  all_pos = (rl > 0.f) && (tl > 0.f) && (il > 0.f);
            float maxc    = fmaxf(rl, fmaxf(tl, il));
            float target  = maxc / 3.f;
            float thresh  = 10.f * target;
            float rw = (all_pos && rl > thresh) ? 1.0f * target / fmaxf(rl, 1e-30f) : 1.0f;
            float tw = (all_pos && tl > thresh) ? 0.5f * target / fmaxf(tl, 1e-30f) : 0.5f;
            float iw = (all_pos && il > thresh) ? 0.1f * target / fmaxf(il, 1e-30f) : 0.1f;

            out[0] = rw * recon + tw * temporal + iw * identity;
            out[1] = recon;
            out[2] = temporal;
            out[3] = identity;

            g_ctr = 0;   // self-reset for next graph replay
        }
    }
}

extern "C" void kernel_launch(void* const* d_in, const int* in_sizes, int n_in,
                              void* d_out, int out_size)
{
    const float* pred = (const float*)d_in[0];
    const float* gt   = (const float*)d_in[1];
    const float* vis  = (const float*)d_in[2];
    float* out = (float*)d_out;
    (void)in_sizes; (void)n_in; (void)out_size;

    main_k<<<NCTA, THREADS>>>(pred, gt, vis);      // 1536 blocks
    finish_k<<<RFIN, 512>>>(out);                  // 128 blocks, fused tail
}